// round 16
// baseline (speedup 1.0000x reference)
#include <cuda_runtime.h>
#include <cstdint>

#define BATCH  16
#define NP     25200
#define TOPKN  2048
#define MAXDET 1000
#define ECAP   6144
#define IPB    128
#define STH    256
#define SN     1024
#define NBK    8192        // fine score buckets per batch (inv>>11)
#define BCAP   24          // per-bucket capacity (avg occupancy ~2.4)
#define FULLM  0xffffffffu
typedef unsigned long long u64;

// ---------------- scratch ----------------
__device__ float4 g_xyxy[BATCH * NP];            // precomputed xyxy per item
__device__ int    g_bcnt[BATCH * NBK];           // bucket counters; reset in k_sortnms
__device__ uint2  g_bdata[BATCH * NBK * BCAP];   // (inv, idx|cls<<16) per bucket

// ---------------- stage 1: score/class -> fine score-bucket scatter + xyxy ----------------
__global__ void __launch_bounds__(STH) k_score(const float* __restrict__ pred) {
    __shared__ float4 s_data4[2721];        // 43536 B, 16B-aligned
    float* s_data = (float*)s_data4;
    int b   = blockIdx.y;
    int it0 = blockIdx.x * IPB;
    int nIt = min(IPB, NP - it0);
    int t = threadIdx.x;

    size_t base  = ((size_t)b * NP + it0) * 85;
    size_t first = base & ~(size_t)3;       // 16B-aligned float offset
    int shift = (int)(base - first);
    int nvec  = (shift + nIt * 85 + 3) >> 2;   // <= 2721; never OOB (total floats % 4 == 0)
    const float4* src = (const float4*)(pred + first);
    unsigned sbase = (unsigned)__cvta_generic_to_shared(s_data4);
    for (int i = t; i < nvec; i += STH) {
        asm volatile("cp.async.cg.shared.global [%0], [%1], 16;"
                     :: "r"(sbase + i * 16), "l"(src + i));
    }
    asm volatile("cp.async.commit_group;\n\tcp.async.wait_group 0;" ::: "memory");
    __syncthreads();

    if (t < nIt) {
        const float* p = s_data + shift + t * 85;   // stride 85: bank-conflict-free
        float obj = p[4];

        float m0 = p[5],  m1 = p[6],  m2 = p[7],  m3 = p[8];
        #pragma unroll
        for (int k = 9; k < 85; k += 4) {
            m0 = fmaxf(m0, p[k]);
            m1 = fmaxf(m1, p[k + 1]);
            m2 = fmaxf(m2, p[k + 2]);
            m3 = fmaxf(m3, p[k + 3]);
        }
        float bv = fmaxf(fmaxf(m0, m1), fmaxf(m2, m3));

        int bi = 0;
        #pragma unroll 8
        for (int k = 79; k >= 0; k--)
            if (p[5 + k] == bv) bi = k;

        float score = __fmul_rn(obj, bv);
        if ((obj > 0.25f) && (score > 0.25f)) {
            unsigned inv = 0x3F800000u - __float_as_uint(score);  // < 0x1000000
            int bucket = (int)(inv >> 11);                        // < 8192
            int pos = atomicAdd(&g_bcnt[b * NBK + bucket], 1);
            if (pos < BCAP)
                g_bdata[(size_t)(b * NBK + bucket) * BCAP + pos] =
                    make_uint2(inv, (unsigned)(it0 + t) | ((unsigned)bi << 16));
        }

        float cx = p[0], cy = p[1], w = p[2], h = p[3];
        float x1 = __fsub_rn(cx, __fmul_rn(w, 0.5f));
        float y1 = __fsub_rn(cy, __fmul_rn(h, 0.5f));
        float x2 = __fadd_rn(cx, __fmul_rn(w, 0.5f));
        float y2 = __fadd_rn(cy, __fmul_rn(h, 0.5f));
        g_xyxy[(size_t)b * NP + it0 + t] = make_float4(x1, y1, x2, y2);
    }
}

// ---------------- smem layout for k_sortnms (no overlays needed) ----------------
#define OFF_FK    0
#define OFF_FV    8192
#define OFF_OBOX  16384
#define OFF_SBOX  49152
#define OFF_SCORE 81920
#define OFF_RNK   90112
#define OFF_CLS   94208
#define OFF_EDGE  96256
#define DYN_TOTAL 120832

__global__ void __launch_bounds__(SN) k_sortnms(float* __restrict__ out) {
    extern __shared__ char raw[];
    unsigned* fk   = (unsigned*)(raw + OFF_FK);
    unsigned* fv   = (unsigned*)(raw + OFF_FV);
    float4*   obox = (float4*)  (raw + OFF_OBOX);
    float4*   sbox = (float4*)  (raw + OFF_SBOX);
    float*    score= (float*)   (raw + OFF_SCORE);
    unsigned short* rnk = (unsigned short*)(raw + OFF_RNK);
    unsigned char*  cls8= (unsigned char*) (raw + OFF_CLS);
    unsigned* edges= (unsigned*)(raw + OFF_EDGE);

    __shared__ int s_wsum[32];
    __shared__ int s_M;
    __shared__ int s_ccnt[81], s_cofs[81], s_pof[81];
    __shared__ int s_ecnt, s_changed;
    __shared__ u64 s_keep[32], s_sup[32];
    __shared__ unsigned s_wbase[32], s_total;

    int b = blockIdx.x, t = threadIdx.x;
    int lane = t & 31, wid = t >> 5;
    size_t bNP = (size_t)b * NP;

    if (t == 0) s_ecnt = 0;

    // ---- load my 8 bucket counts, clamp, reset ----
    int4 c0 = *(int4*)&g_bcnt[b * NBK + t * 8];
    int4 c1 = *(int4*)&g_bcnt[b * NBK + t * 8 + 4];
    int cnts[8] = { min(c0.x, BCAP), min(c0.y, BCAP), min(c0.z, BCAP), min(c0.w, BCAP),
                    min(c1.x, BCAP), min(c1.y, BCAP), min(c1.z, BCAP), min(c1.w, BCAP) };
    *(int4*)&g_bcnt[b * NBK + t * 8]     = make_int4(0, 0, 0, 0);
    *(int4*)&g_bcnt[b * NBK + t * 8 + 4] = make_int4(0, 0, 0, 0);
    int sum = cnts[0] + cnts[1] + cnts[2] + cnts[3]
            + cnts[4] + cnts[5] + cnts[6] + cnts[7];

    // ---- block exclusive scan over 1024 thread-sums ----
    int incl = sum;
    #pragma unroll
    for (int d = 1; d < 32; d <<= 1) {
        int n = __shfl_up_sync(FULLM, incl, d);
        if (lane >= d) incl += n;
    }
    if (lane == 31) s_wsum[wid] = incl;
    __syncthreads();
    if (t < 32) {
        int v = s_wsum[t], inc2 = v;
        #pragma unroll
        for (int d = 1; d < 32; d <<= 1) {
            int n = __shfl_up_sync(FULLM, inc2, d);
            if (t >= d) inc2 += n;
        }
        s_wsum[t] = inc2 - v;
    }
    __syncthreads();
    int base = s_wsum[wid] + incl - sum;
    if (t == SN - 1) s_M = base + sum;

    // ---- per-thread bucket rank-sort directly into final positions ----
    // global order = (bucket asc, (inv<<15)|idx asc); keys all distinct -> deterministic;
    // truncation at TOPKN == exact stable top-k
    int start = base;
    #pragma unroll
    for (int k = 0; k < 8; k++) {
        int n = cnts[k];
        if (n > 0 && start < TOPKN) {
            const uint2* bd = &g_bdata[(size_t)(b * NBK + t * 8 + k) * BCAP];
            for (int x = 0; x < n; x++) {
                uint2 e = bd[x];
                u64 kx = ((u64)e.x << 15) | (u64)(e.y & 0x7FFFu);
                int rank = 0;
                for (int y = 0; y < n; y++) {
                    uint2 ey = bd[y];
                    u64 ky = ((u64)ey.x << 15) | (u64)(ey.y & 0x7FFFu);
                    rank += (ky < kx);
                }
                int pos = start + rank;
                if (pos < TOPKN) { fk[pos] = e.x; fv[pos] = e.y; }
            }
        }
        start += n;
    }
    if (t < 81) s_ccnt[t] = 0;
    __syncthreads();
    int total = min(s_M, TOPKN);

    // ---- gather top-2048 into smem (single aligned LDG.128 per item) ----
    #pragma unroll
    for (int rr = 0; rr < TOPKN / SN; rr++) {
        int r = t + SN * rr;
        if (r >= total) {
            obox[r]  = make_float4(0.f, 0.f, 0.f, 0.f);
            score[r] = 0.f;
            cls8[r]  = 0;
            continue;
        }
        int idx = (int)(fv[r] & 0xFFFFu);
        int cls = (int)((fv[r] >> 16) & 0x7Fu);
        obox[r]  = g_xyxy[bNP + idx];
        score[r] = __uint_as_float(0x3F800000u - fk[r]);
        cls8[r]  = (unsigned char)cls;
        atomicAdd(&s_ccnt[cls], 1);
    }
    __syncthreads();
    if (t == 0) {
        int run = 0, prun = 0;
        for (int c = 0; c < 80; c++) {
            int n = s_ccnt[c];
            s_cofs[c] = run;  run  += n;
            s_pof[c]  = prun; prun += (n * (n - 1)) >> 1;
        }
        s_cofs[80] = run;
        s_pof[80]  = prun;
    }
    __syncthreads();
    if (t < 80) s_ccnt[t] = s_cofs[t];   // running positions
    __syncthreads();

    // ---- class-grouped scatter of shifted boxes ----
    #pragma unroll
    for (int rr = 0; rr < TOPKN / SN; rr++) {
        int r = t + SN * rr;
        if (r >= total) continue;
        int cls = (int)((fv[r] >> 16) & 0x7Fu);
        int slot = atomicAdd(&s_ccnt[cls], 1);
        float4 bx = obox[r];
        float c = __fmul_rn((float)cls, 4096.0f);
        sbox[slot] = make_float4(__fadd_rn(bx.x, c), __fadd_rn(bx.y, c),
                                 __fadd_rn(bx.z, c), __fadd_rn(bx.w, c));
        rnk[slot] = (unsigned short)r;
    }
    __syncthreads();

    // ---- globally flattened within-class pairs: all 1024 threads share the work ----
    int totalPairs = s_pof[80];
    for (int p = t; p < totalPairs; p += SN) {
        // binary search class: s_pof[c] <= p < s_pof[c+1]
        int lo = 0, hi = 80;
        while (hi - lo > 1) {
            int mid = (lo + hi) >> 1;
            if (s_pof[mid] <= p) lo = mid; else hi = mid;
        }
        int c = lo;
        int pp = p - s_pof[c];
        int clo = s_cofs[c];
        // triangular decode within class
        int j = (int)(0.5f * (1.0f + sqrtf(8.0f * (float)pp + 1.0f)));
        while ((j * (j - 1)) >> 1 > pp) j--;
        while ((j * (j + 1)) >> 1 <= pp) j++;
        int i = pp - ((j * (j - 1)) >> 1);

        float4 A = sbox[clo + j];
        float4 B = sbox[clo + i];
        float ltx = fmaxf(A.x, B.x);
        float lty = fmaxf(A.y, B.y);
        float rbx = fminf(A.z, B.z);
        float rby = fminf(A.w, B.w);
        float ww = fmaxf(__fsub_rn(rbx, ltx), 0.0f);
        float hh = fmaxf(__fsub_rn(rby, lty), 0.0f);
        float inter = __fmul_rn(ww, hh);
        if (inter > 0.0f) {
            float areaA = __fmul_rn(__fsub_rn(A.z, A.x), __fsub_rn(A.w, A.y));
            float areaB = __fmul_rn(__fsub_rn(B.z, B.x), __fsub_rn(B.w, B.y));
            float denom = __fadd_rn(__fsub_rn(__fadd_rn(areaA, areaB), inter), 1e-7f);
            bool bit;
            if (inter > __fmul_rn(0.4501f, denom))       bit = true;
            else if (inter <= __fmul_rn(0.4499f, denom)) bit = false;
            else bit = (__fdiv_rn(inter, denom) > 0.45f);
            if (bit) {
                int ri = rnk[clo + i], rj = rnk[clo + j];
                int lw = min(ri, rj), hi2 = max(ri, rj);
                int pos = atomicAdd(&s_ecnt, 1);
                if (pos < ECAP)
                    edges[pos] = ((unsigned)lw << 16) | (unsigned)hi2;
            }
        }
    }
    __syncthreads();
    int E = min(s_ecnt, ECAP);

    if (t < 32) {
        int bb = t * 64;
        s_keep[t] = (total >= bb + 64) ? ~0ull
                  : (total <= bb) ? 0ull : ((1ull << (total - bb)) - 1ull);
    }
    __syncthreads();

    // ---- Jacobi fixpoint (DAG, edges i<j) ----
    int changed;
    do {
        if (t < 32) s_sup[t] = 0ull;
        __syncthreads();
        for (int e = t; e < E; e += SN) {
            unsigned ed = edges[e];
            int i = (int)(ed >> 16), j = (int)(ed & 0xFFFFu);
            if ((s_keep[i >> 6] >> (i & 63)) & 1ull)
                atomicOr(&s_sup[j >> 6], 1ull << (j & 63));
        }
        __syncthreads();
        if (t == 0) s_changed = 0;
        __syncthreads();
        if (t < 32) {
            int bb = t * 64;
            u64 valid = (total >= bb + 64) ? ~0ull
                      : (total <= bb) ? 0ull : ((1ull << (total - bb)) - 1ull);
            u64 nk = valid & ~s_sup[t];
            if (nk != s_keep[t]) { s_keep[t] = nk; s_changed = 1; }
        }
        __syncthreads();
        changed = s_changed;
    } while (changed);

    // ---- output ----
    if (wid == 0) {
        unsigned cnt2 = (unsigned)__popcll(s_keep[lane]), incl2 = cnt2;
        #pragma unroll
        for (int d = 1; d < 32; d <<= 1) {
            unsigned n = __shfl_up_sync(FULLM, incl2, d);
            if (lane >= d) incl2 += n;
        }
        s_wbase[lane] = incl2 - cnt2;
        if (lane == 31) s_total = incl2;
    }
    __syncthreads();

    #pragma unroll
    for (int r = 0; r < TOPKN / SN; r++) {
        int gbit = t + SN * r;
        int word = gbit >> 6, bit = gbit & 63;
        u64 kw = s_keep[word];
        if ((kw >> bit) & 1ull) {
            unsigned rank = s_wbase[word] +
                            (unsigned)__popcll(kw & (((u64)1 << bit) - 1ull));
            if (rank < MAXDET) {
                float4 bx = obox[gbit];
                float* o = out + ((size_t)b * MAXDET + rank) * 6;
                o[0] = bx.x; o[1] = bx.y; o[2] = bx.z; o[3] = bx.w;
                o[4] = score[gbit];
                o[5] = (float)cls8[gbit];
            }
        }
    }
    unsigned fillstart = min(s_total, (unsigned)MAXDET);
    for (unsigned m = fillstart + t; m < MAXDET; m += SN) {
        float* o = out + ((size_t)b * MAXDET + m) * 6;
        o[0] = 0.f; o[1] = 0.f; o[2] = 0.f; o[3] = 0.f; o[4] = 0.f; o[5] = -1.f;
    }
}

// ---------------- launch ----------------
extern "C" void kernel_launch(void* const* d_in, const int* in_sizes, int n_in,
                              void* d_out, int out_size) {
    (void)in_sizes; (void)n_in; (void)out_size;
    const float* pred = (const float*)d_in[0];
    float* out = (float*)d_out;

    static bool attr_set = false;
    if (!attr_set) {
        cudaFuncSetAttribute(k_sortnms, cudaFuncAttributeMaxDynamicSharedMemorySize,
                             DYN_TOTAL);
        attr_set = true;
    }

    k_score<<<dim3((NP + IPB - 1) / IPB, BATCH), STH>>>(pred);
    k_sortnms<<<BATCH, SN, DYN_TOTAL>>>(out);
}

// round 17
// speedup vs baseline: 1.4247x; 1.4247x over previous
#include <cuda_runtime.h>
#include <cstdint>

#define BATCH  16
#define NP     25200
#define TOPKN  2048
#define MAXDET 1000
#define CANDN  4096
#define ECAP   6144
#define IPB    128
#define STH    256
#define SN     1024
#define FULLM  0xffffffffu
typedef unsigned long long u64;

// ---------------- scratch ----------------
__device__ unsigned g_key32[BATCH * NP];   // (inv<<7)|cls, 0xFFFFFFFF = invalid
__device__ float4   g_xyxy[BATCH * NP];    // precomputed xyxy per item
__device__ int      g_hist[BATCH * 132];   // bucket = inv>>17 (valid only); reset in k_sortnms

// ---------------- stage 1: thread-per-item score/class/key + xyxy (cp.async staging) ----------------
__global__ void __launch_bounds__(STH) k_score(const float* __restrict__ pred) {
    __shared__ float4 s_data4[2721];        // 43536 B, 16B-aligned
    __shared__ int    s_h[128];
    float* s_data = (float*)s_data4;
    int b   = blockIdx.y;
    int it0 = blockIdx.x * IPB;
    int nIt = min(IPB, NP - it0);
    int t = threadIdx.x;

    if (t < 128) s_h[t] = 0;

    size_t base  = ((size_t)b * NP + it0) * 85;
    size_t first = base & ~(size_t)3;       // 16B-aligned float offset
    int shift = (int)(base - first);
    int nvec  = (shift + nIt * 85 + 3) >> 2;   // <= 2721; never OOB (total floats % 4 == 0)
    const float4* src = (const float4*)(pred + first);
    unsigned sbase = (unsigned)__cvta_generic_to_shared(s_data4);
    for (int i = t; i < nvec; i += STH) {
        asm volatile("cp.async.cg.shared.global [%0], [%1], 16;"
                     :: "r"(sbase + i * 16), "l"(src + i));
    }
    asm volatile("cp.async.commit_group;\n\tcp.async.wait_group 0;" ::: "memory");
    __syncthreads();

    if (t < nIt) {
        const float* p = s_data + shift + t * 85;   // stride 85: bank-conflict-free
        float obj = p[4];

        float m0 = p[5],  m1 = p[6],  m2 = p[7],  m3 = p[8];
        #pragma unroll
        for (int k = 9; k < 85; k += 4) {
            m0 = fmaxf(m0, p[k]);
            m1 = fmaxf(m1, p[k + 1]);
            m2 = fmaxf(m2, p[k + 2]);
            m3 = fmaxf(m3, p[k + 3]);
        }
        float bv = fmaxf(fmaxf(m0, m1), fmaxf(m2, m3));

        int bi = 0;
        #pragma unroll 8
        for (int k = 79; k >= 0; k--)
            if (p[5 + k] == bv) bi = k;

        float score = __fmul_rn(obj, bv);
        bool valid = (obj > 0.25f) && (score > 0.25f);
        unsigned kk = 0xFFFFFFFFu;
        if (valid) {
            unsigned inv = 0x3F800000u - __float_as_uint(score);  // < 0x1000000
            kk = (inv << 7) | (unsigned)bi;
            atomicAdd(&s_h[inv >> 17], 1);
        }
        g_key32[(size_t)b * NP + it0 + t] = kk;

        float cx = p[0], cy = p[1], w = p[2], h = p[3];
        float x1 = __fsub_rn(cx, __fmul_rn(w, 0.5f));
        float y1 = __fsub_rn(cy, __fmul_rn(h, 0.5f));
        float x2 = __fadd_rn(cx, __fmul_rn(w, 0.5f));
        float y2 = __fadd_rn(cy, __fmul_rn(h, 0.5f));
        g_xyxy[(size_t)b * NP + it0 + t] = make_float4(x1, y1, x2, y2);
    }
    __syncthreads();
    if (t < 128) {
        int v = s_h[t];
        if (v) atomicAdd(&g_hist[b * 132 + t], v);
    }
}

// ---------------- smem layout for k_sortnms (explicit overlays by liveness) ----------------
// sk/sv [0, 32768)       bucket-scattered candidates; dead after rank sort
// fk/fv [32768, 65536)   sorted; fk dead after gather, fv after class-scatter
// obox  [65536, 98304)  score [98304, 106496)  rnk [106496, 110592)  cls8 [110592, 112640)
// sbox  [0, 32768)       overlays dead sk/sv
// edges [32768, 57344)   overlays dead fk/fv
#define OFF_SK    0
#define OFF_SV    16384
#define OFF_FK    32768
#define OFF_FV    49152
#define OFF_OBOX  65536
#define OFF_SCORE 98304
#define OFF_RNK   106496
#define OFF_CLS   110592
#define OFF_SBOX  0
#define OFF_EDGE  32768
#define DYN_TOTAL 112640

__global__ void __launch_bounds__(SN) k_sortnms(float* __restrict__ out) {
    extern __shared__ char raw[];
    unsigned* sk   = (unsigned*)(raw + OFF_SK);
    unsigned* sv   = (unsigned*)(raw + OFF_SV);
    unsigned* fk   = (unsigned*)(raw + OFF_FK);
    unsigned* fv   = (unsigned*)(raw + OFF_FV);
    float4*   obox = (float4*)  (raw + OFF_OBOX);
    float4*   sbox = (float4*)  (raw + OFF_SBOX);
    float*    score= (float*)   (raw + OFF_SCORE);
    unsigned short* rnk = (unsigned short*)(raw + OFF_RNK);
    unsigned char*  cls8= (unsigned char*) (raw + OFF_CLS);
    unsigned* edges= (unsigned*)(raw + OFF_EDGE);

    __shared__ int s_bh[256];
    __shared__ int s_hist[128];
    __shared__ int s_cut, s_M;
    __shared__ int s_ccnt[81], s_cofs[81];
    __shared__ int s_ecnt, s_changed;
    __shared__ u64 s_keep[32], s_sup[32];
    __shared__ unsigned s_wbase[32], s_total;

    int b = blockIdx.x, t = threadIdx.x;
    int lane = t & 31, wid = t >> 5;
    size_t bNP = (size_t)b * NP;

    // ---- load my 28 keys into registers (7 coalesced uint4 LDGs, high MLP) ----
    uint4 kreg[7];
    const uint4* gk = (const uint4*)(g_key32 + bNP);
    #pragma unroll
    for (int r = 0; r < 7; r++) {
        int i = r * SN + t;
        kreg[r] = (i < NP / 4) ? gk[i] : make_uint4(FULLM, FULLM, FULLM, FULLM);
    }

    if (t < 128) { s_hist[t] = g_hist[b * 132 + t]; g_hist[b * 132 + t] = 0; }
    if (t < 256) s_bh[t] = 0;
    __syncthreads();
    if (t == 0) {
        int cum = 0, c = 128;
        for (int i = 0; i < 128; i++) {
            cum += s_hist[i];
            if (cum >= TOPKN) { c = i; break; }
        }
        s_cut = c;
        s_ecnt = 0;
    }
    __syncthreads();
    unsigned cut = (unsigned)s_cut;
    unsigned limit = min((cut + 1u) << 17, 1u << 24);
    int end_bit = 32 - __clz(limit - 1u);
    int bsh = (end_bit > 8) ? (end_bit - 8) : 0;   // bucket = inv >> bsh < 256

    // ---- pass 1: bucket histogram from registers ----
    #pragma unroll
    for (int r = 0; r < 7; r++) {
        unsigned kkv[4] = { kreg[r].x, kreg[r].y, kreg[r].z, kreg[r].w };
        #pragma unroll
        for (int j = 0; j < 4; j++)
            if ((kkv[j] >> 24) <= cut)
                atomicAdd(&s_bh[(kkv[j] >> 7) >> bsh], 1);
    }
    __syncthreads();
    // ---- one-warp exclusive scan over 256 buckets (8 per lane) ----
    if (t < 32) {
        int loc[8], run = 0;
        #pragma unroll
        for (int k = 0; k < 8; k++) { loc[k] = run; run += s_bh[t * 8 + k]; }
        int inc = run;
        #pragma unroll
        for (int d = 1; d < 32; d <<= 1) {
            int n = __shfl_up_sync(FULLM, inc, d);
            if (t >= d) inc += n;
        }
        int base = inc - run;
        #pragma unroll
        for (int k = 0; k < 8; k++) s_bh[t * 8 + k] = base + loc[k];
        if (t == 31) s_M = inc;
    }
    __syncthreads();
    int M = min(s_M, CANDN);

    // ---- pass 2: scatter from registers into bucket-sorted array (unordered) ----
    #pragma unroll
    for (int r = 0; r < 7; r++) {
        unsigned kkv[4] = { kreg[r].x, kreg[r].y, kreg[r].z, kreg[r].w };
        #pragma unroll
        for (int j = 0; j < 4; j++) {
            unsigned kk = kkv[j];
            if ((kk >> 24) <= cut) {
                unsigned inv = kk >> 7;
                int pos = atomicAdd(&s_bh[inv >> bsh], 1);
                if (pos < CANDN) {
                    sk[pos] = inv;
                    sv[pos] = (unsigned)((r * SN + t) * 4 + j) | ((kk & 0x7Fu) << 16);
                }
            }
        }
    }
    __syncthreads();
    // ---- per-bucket exact-rank sort; keys (inv<<15|idx) all distinct -> deterministic ----
    #pragma unroll
    for (int k8 = 0; k8 < 8; k8++) {
        int bb = wid * 8 + k8;
        int st = (bb == 0) ? 0 : min(s_bh[bb - 1], CANDN);
        int en = min(s_bh[bb], CANDN);
        for (int x = st + lane; x < en; x += 32) {
            unsigned kx = sk[x], vx = sv[x];
            u64 key = ((u64)kx << 15) | (u64)(vx & 0x7FFFu);
            int rank = 0;
            for (int y = st; y < en; y++) {
                u64 ky = ((u64)sk[y] << 15) | (u64)(sv[y] & 0x7FFFu);
                rank += (ky < key);
            }
            fk[st + rank] = kx; fv[st + rank] = vx;
        }
    }
    if (t < 81) s_ccnt[t] = 0;
    __syncthreads();
    int total = min(M, TOPKN);

    // ---- gather top-2048 into smem (single aligned LDG.128 per item) ----
    #pragma unroll
    for (int rr = 0; rr < TOPKN / SN; rr++) {
        int r = t + SN * rr;
        if (r >= total) {
            obox[r]  = make_float4(0.f, 0.f, 0.f, 0.f);
            score[r] = 0.f;
            cls8[r]  = 0;
            continue;
        }
        int idx = (int)(fv[r] & 0x7FFFu);
        int cls = (int)((fv[r] >> 16) & 0x7Fu);
        obox[r]  = g_xyxy[bNP + idx];
        score[r] = __uint_as_float(0x3F800000u - fk[r]);
        cls8[r]  = (unsigned char)cls;
        atomicAdd(&s_ccnt[cls], 1);
    }
    __syncthreads();
    if (t == 0) {
        int run = 0;
        for (int c = 0; c < 80; c++) { s_cofs[c] = run; run += s_ccnt[c]; }
        s_cofs[80] = run;
    }
    __syncthreads();
    if (t < 80) s_ccnt[t] = s_cofs[t];   // running positions
    __syncthreads();

    // ---- class-grouped scatter of shifted boxes (sbox overlays dead sk/sv) ----
    #pragma unroll
    for (int rr = 0; rr < TOPKN / SN; rr++) {
        int r = t + SN * rr;
        if (r >= total) continue;
        int cls = (int)((fv[r] >> 16) & 0x7Fu);
        int slot = atomicAdd(&s_ccnt[cls], 1);
        float4 bx = obox[r];
        float c = __fmul_rn((float)cls, 4096.0f);
        sbox[slot] = make_float4(__fadd_rn(bx.x, c), __fadd_rn(bx.y, c),
                                 __fadd_rn(bx.z, c), __fadd_rn(bx.w, c));
        rnk[slot] = (unsigned short)r;
    }
    __syncthreads();

    // ---- within-class pairs flattened across lanes; 32 warps over 80 classes ----
    for (int c = wid; c < 80; c += 32) {
        int lo = s_cofs[c], n = s_cofs[c + 1] - lo;
        int npairs = (n * (n - 1)) >> 1;
        for (int p = lane; p < npairs; p += 32) {
            int j = (int)(0.5f * (1.0f + sqrtf(8.0f * (float)p + 1.0f)));
            while ((j * (j - 1)) >> 1 > p) j--;
            while ((j * (j + 1)) >> 1 <= p) j++;
            int i = p - ((j * (j - 1)) >> 1);

            float4 A = sbox[lo + j];
            float4 B = sbox[lo + i];
            float ltx = fmaxf(A.x, B.x);
            float lty = fmaxf(A.y, B.y);
            float rbx = fminf(A.z, B.z);
            float rby = fminf(A.w, B.w);
            float ww = fmaxf(__fsub_rn(rbx, ltx), 0.0f);
            float hh = fmaxf(__fsub_rn(rby, lty), 0.0f);
            float inter = __fmul_rn(ww, hh);
            if (inter > 0.0f) {
                float areaA = __fmul_rn(__fsub_rn(A.z, A.x), __fsub_rn(A.w, A.y));
                float areaB = __fmul_rn(__fsub_rn(B.z, B.x), __fsub_rn(B.w, B.y));
                float denom = __fadd_rn(__fsub_rn(__fadd_rn(areaA, areaB), inter), 1e-7f);
                bool bit;
                if (inter > __fmul_rn(0.4501f, denom))       bit = true;
                else if (inter <= __fmul_rn(0.4499f, denom)) bit = false;
                else bit = (__fdiv_rn(inter, denom) > 0.45f);
                if (bit) {
                    int ri = rnk[lo + i], rj = rnk[lo + j];
                    int lw = min(ri, rj), hi2 = max(ri, rj);
                    int pos = atomicAdd(&s_ecnt, 1);
                    if (pos < ECAP)
                        edges[pos] = ((unsigned)lw << 16) | (unsigned)hi2;
                }
            }
        }
    }
    __syncthreads();
    int E = min(s_ecnt, ECAP);

    if (t < 32) {
        int bb = t * 64;
        s_keep[t] = (total >= bb + 64) ? ~0ull
                  : (total <= bb) ? 0ull : ((1ull << (total - bb)) - 1ull);
    }
    __syncthreads();

    // ---- Jacobi fixpoint (DAG, edges i<j) ----
    int changed;
    do {
        if (t < 32) s_sup[t] = 0ull;
        __syncthreads();
        for (int e = t; e < E; e += SN) {
            unsigned ed = edges[e];
            int i = (int)(ed >> 16), j = (int)(ed & 0xFFFFu);
            if ((s_keep[i >> 6] >> (i & 63)) & 1ull)
                atomicOr(&s_sup[j >> 6], 1ull << (j & 63));
        }
        __syncthreads();
        if (t == 0) s_changed = 0;
        __syncthreads();
        if (t < 32) {
            int bb = t * 64;
            u64 valid = (total >= bb + 64) ? ~0ull
                      : (total <= bb) ? 0ull : ((1ull << (total - bb)) - 1ull);
            u64 nk = valid & ~s_sup[t];
            if (nk != s_keep[t]) { s_keep[t] = nk; s_changed = 1; }
        }
        __syncthreads();
        changed = s_changed;
    } while (changed);

    // ---- output ----
    if (wid == 0) {
        unsigned cnt2 = (unsigned)__popcll(s_keep[lane]), incl2 = cnt2;
        #pragma unroll
        for (int d = 1; d < 32; d <<= 1) {
            unsigned n = __shfl_up_sync(FULLM, incl2, d);
            if (lane >= d) incl2 += n;
        }
        s_wbase[lane] = incl2 - cnt2;
        if (lane == 31) s_total = incl2;
    }
    __syncthreads();

    #pragma unroll
    for (int r = 0; r < TOPKN / SN; r++) {
        int gbit = t + SN * r;
        int word = gbit >> 6, bit = gbit & 63;
        u64 kw = s_keep[word];
        if ((kw >> bit) & 1ull) {
            unsigned rank = s_wbase[word] +
                            (unsigned)__popcll(kw & (((u64)1 << bit) - 1ull));
            if (rank < MAXDET) {
                float4 bx = obox[gbit];
                float* o = out + ((size_t)b * MAXDET + rank) * 6;
                o[0] = bx.x; o[1] = bx.y; o[2] = bx.z; o[3] = bx.w;
                o[4] = score[gbit];
                o[5] = (float)cls8[gbit];
            }
        }
    }
    unsigned fillstart = min(s_total, (unsigned)MAXDET);
    for (unsigned m = fillstart + t; m < MAXDET; m += SN) {
        float* o = out + ((size_t)b * MAXDET + m) * 6;
        o[0] = 0.f; o[1] = 0.f; o[2] = 0.f; o[3] = 0.f; o[4] = 0.f; o[5] = -1.f;
    }
}

// ---------------- launch ----------------
extern "C" void kernel_launch(void* const* d_in, const int* in_sizes, int n_in,
                              void* d_out, int out_size) {
    (void)in_sizes; (void)n_in; (void)out_size;
    const float* pred = (const float*)d_in[0];
    float* out = (float*)d_out;

    static bool attr_set = false;
    if (!attr_set) {
        cudaFuncSetAttribute(k_sortnms, cudaFuncAttributeMaxDynamicSharedMemorySize,
                             DYN_TOTAL);
        attr_set = true;
    }

    k_score<<<dim3((NP + IPB - 1) / IPB, BATCH), STH>>>(pred);
    k_sortnms<<<BATCH, SN, DYN_TOTAL>>>(out);
}